// round 1
// baseline (speedup 1.0000x reference)
#include <cuda_runtime.h>
#include <cuda_bf16.h>
#include <math.h>

#define NMAX 100000
#define EMAX 1600000
#define FDIM 128
#define FFDIM 512

// ---------------- scratch (static device globals; no allocation) ----------------
__device__ float g_xlr[(size_t)NMAX * 256];   // [N, 256]: cols 0..127 = xl, 128..255 = xr
__device__ float g_ex [(size_t)EMAX * 8];     // exp(e) per edge/head
__device__ float g_den[(size_t)NMAX * 8];     // softmax denominators per node/head
__device__ float g_h  [(size_t)NMAX * FDIM];  // GAT output (+bias), residual stream
__device__ float g_t  [(size_t)NMAX * FDIM];  // LN1 output
__device__ float g_u  [(size_t)NMAX * FFDIM]; // silu(t@W1+b)
__device__ float g_v  [(size_t)NMAX * FDIM];  // u@W2+b
__device__ float g_wcat[FDIM * 256];          // [Wl | Wr] concatenated along cols
__device__ float g_bcat[256];

// ---------------- weight concat prep ----------------
__global__ void prep_wcat(const float* __restrict__ Wl, const float* __restrict__ Wr,
                          const float* __restrict__ bl, const float* __restrict__ br) {
    int i = blockIdx.x * blockDim.x + threadIdx.x;
    if (i < FDIM * 256) {
        int k = i >> 8, j = i & 255;
        g_wcat[i] = (j < 128) ? Wl[k * 128 + j] : Wr[k * 128 + (j - 128)];
    }
    if (i < 256) g_bcat[i] = (i < 128) ? bl[i] : br[i - 128];
}

// ---------------- init: h = bias_gat (broadcast per row) ----------------
__global__ void init_h(const float* __restrict__ bias, int n) {
    int i = blockIdx.x * blockDim.x + threadIdx.x;
    if (i < n * FDIM) g_h[i] = bias[i & 127];
}

// ---------------- SGEMM: C[M,N] = A[M,K] @ B[K,N] + bias, optional silu ----------------
// 128x128 block tile, BK=8, 256 threads, 8x8 per thread.
__global__ void __launch_bounds__(256, 2)
sgemm(const float* __restrict__ A, const float* __restrict__ Bm,
      float* __restrict__ C, const float* __restrict__ bias,
      int M, int N, int K, int act) {
    __shared__ float As[8][128];
    __shared__ float Bs[8][128];
    const int tid  = threadIdx.x;
    const int brow = blockIdx.y * 128;
    const int bcol = blockIdx.x * 128;

    const int a_row = tid >> 1;
    const int a_col = (tid & 1) << 2;
    const int b_row = tid >> 5;
    const int b_col = (tid & 31) << 2;

    const int ty = (tid >> 4) << 3;   // 0..120 step 8
    const int tx = (tid & 15) << 3;   // 0..120 step 8

    float acc[8][8];
#pragma unroll
    for (int i = 0; i < 8; i++)
#pragma unroll
        for (int j = 0; j < 8; j++) acc[i][j] = 0.f;

    const int grow = brow + a_row;
    const bool a_valid = (grow < M);
    const float* Aptr = A + (size_t)grow * K + a_col;

    for (int k0 = 0; k0 < K; k0 += 8) {
        float4 a4 = a_valid ? *(const float4*)(Aptr + k0) : make_float4(0.f, 0.f, 0.f, 0.f);
        As[a_col + 0][a_row] = a4.x;
        As[a_col + 1][a_row] = a4.y;
        As[a_col + 2][a_row] = a4.z;
        As[a_col + 3][a_row] = a4.w;
        *(float4*)&Bs[b_row][b_col] =
            *(const float4*)(Bm + (size_t)(k0 + b_row) * N + bcol + b_col);
        __syncthreads();
#pragma unroll
        for (int k = 0; k < 8; k++) {
            float4 a0 = *(const float4*)&As[k][ty];
            float4 a1 = *(const float4*)&As[k][ty + 4];
            float4 b0 = *(const float4*)&Bs[k][tx];
            float4 b1 = *(const float4*)&Bs[k][tx + 4];
            float ar[8] = {a0.x, a0.y, a0.z, a0.w, a1.x, a1.y, a1.z, a1.w};
            float br_[8] = {b0.x, b0.y, b0.z, b0.w, b1.x, b1.y, b1.z, b1.w};
#pragma unroll
            for (int i = 0; i < 8; i++)
#pragma unroll
                for (int j = 0; j < 8; j++) acc[i][j] += ar[i] * br_[j];
        }
        __syncthreads();
    }

#pragma unroll
    for (int i = 0; i < 8; i++) {
        int row = brow + ty + i;
        if (row >= M) continue;
        float out[8];
#pragma unroll
        for (int j = 0; j < 8; j++) {
            float c = acc[i][j] + bias[bcol + tx + j];
            if (act) c = c / (1.f + expf(-c));   // silu
            out[j] = c;
        }
        float* crow = C + (size_t)row * N + bcol + tx;
        *(float4*)(crow)     = make_float4(out[0], out[1], out[2], out[3]);
        *(float4*)(crow + 4) = make_float4(out[4], out[5], out[6], out[7]);
    }
}

// ---------------- edge pass 1: scores -> exp -> denom atomics ----------------
// one warp per edge; lane covers 4 channels (float4); head = lane>>2
__global__ void edge_score(const int* __restrict__ ei, const float* __restrict__ att, int E_) {
    int idx = blockIdx.x * blockDim.x + threadIdx.x;
    int e = idx >> 5, lane = idx & 31;
    if (e >= E_) return;
    int src = ei[e];
    int dst = ei[E_ + e];
    const float4* xlr4 = (const float4*)g_xlr;
    float4 a = xlr4[(size_t)src * 64 + lane];        // xl[src]
    float4 b = xlr4[(size_t)dst * 64 + 32 + lane];   // xr[dst]
    float4 s;
    s.x = a.x + b.x; s.x = s.x > 0.f ? s.x : 0.2f * s.x;
    s.y = a.y + b.y; s.y = s.y > 0.f ? s.y : 0.2f * s.y;
    s.z = a.z + b.z; s.z = s.z > 0.f ? s.z : 0.2f * s.z;
    s.w = a.w + b.w; s.w = s.w > 0.f ? s.w : 0.2f * s.w;
    float4 w = ((const float4*)att)[lane];
    float p = s.x * w.x + s.y * w.y + s.z * w.z + s.w * w.w;
    p += __shfl_xor_sync(0xffffffffu, p, 1);
    p += __shfl_xor_sync(0xffffffffu, p, 2);
    if ((lane & 3) == 0) {
        int h = lane >> 2;
        float ex = expf(p);  // scores are O(1); softmax-max shift unnecessary
        g_ex[(size_t)e * 8 + h] = ex;
        atomicAdd(&g_den[(size_t)dst * 8 + h], ex);
    }
}

// ---------------- edge pass 2: alpha * xl[src] scatter-add into h[dst] ----------------
__global__ void edge_aggr(const int* __restrict__ ei, int E_) {
    int idx = blockIdx.x * blockDim.x + threadIdx.x;
    int e = idx >> 5, lane = idx & 31;
    if (e >= E_) return;
    int src = ei[e];
    int dst = ei[E_ + e];
    int h = lane >> 2;
    float alpha = g_ex[(size_t)e * 8 + h] / g_den[(size_t)dst * 8 + h];
    float4 a = ((const float4*)g_xlr)[(size_t)src * 64 + lane];
    float* hp = g_h + (size_t)dst * 128 + lane * 4;
    atomicAdd(hp + 0, a.x * alpha);
    atomicAdd(hp + 1, a.y * alpha);
    atomicAdd(hp + 2, a.z * alpha);
    atomicAdd(hp + 3, a.w * alpha);
}

// ---------------- LayerNorm (warp per node); optional residual add ----------------
__global__ void ln_kernel(const float* __restrict__ in, const float* __restrict__ res,
                          const float* __restrict__ g, const float* __restrict__ b,
                          float* __restrict__ out, int n) {
    int warp = (blockIdx.x * blockDim.x + threadIdx.x) >> 5;
    int lane = threadIdx.x & 31;
    if (warp >= n) return;
    float4 v = ((const float4*)(in + (size_t)warp * 128))[lane];
    if (res) {
        float4 r = ((const float4*)(res + (size_t)warp * 128))[lane];
        v.x += r.x; v.y += r.y; v.z += r.z; v.w += r.w;
    }
    float s  = v.x + v.y + v.z + v.w;
    float sq = v.x * v.x + v.y * v.y + v.z * v.z + v.w * v.w;
#pragma unroll
    for (int o = 16; o; o >>= 1) {
        s  += __shfl_xor_sync(0xffffffffu, s, o);
        sq += __shfl_xor_sync(0xffffffffu, sq, o);
    }
    float mu = s * (1.f / 128.f);
    float var = sq * (1.f / 128.f) - mu * mu;
    float rstd = rsqrtf(var + 1e-5f);
    float4 gg = ((const float4*)g)[lane];
    float4 bb = ((const float4*)b)[lane];
    float4 o4;
    o4.x = (v.x - mu) * rstd * gg.x + bb.x;
    o4.y = (v.y - mu) * rstd * gg.y + bb.y;
    o4.z = (v.z - mu) * rstd * gg.z + bb.z;
    o4.w = (v.w - mu) * rstd * gg.w + bb.w;
    ((float4*)(out + (size_t)warp * 128))[lane] = o4;
}

// ---------------- launch ----------------
extern "C" void kernel_launch(void* const* d_in, const int* in_sizes, int n_in,
                              void* d_out, int out_size) {
    const float* x        = (const float*)d_in[0];
    const int*   ei       = (const int*)  d_in[1];
    const float* Wl       = (const float*)d_in[2];
    const float* bl       = (const float*)d_in[3];
    const float* Wr       = (const float*)d_in[4];
    const float* br       = (const float*)d_in[5];
    const float* att      = (const float*)d_in[6];
    const float* bias_gat = (const float*)d_in[7];
    const float* g1       = (const float*)d_in[8];
    const float* bn1      = (const float*)d_in[9];
    const float* W1       = (const float*)d_in[10];
    const float* bW1      = (const float*)d_in[11];
    const float* W2       = (const float*)d_in[12];
    const float* bW2      = (const float*)d_in[13];
    const float* g2       = (const float*)d_in[14];
    const float* bn2      = (const float*)d_in[15];
    float* out = (float*)d_out;

    const int n = in_sizes[0] / FDIM;      // 100000
    const int E = in_sizes[1] / 2;         // 1600000

    float *p_xlr, *p_t, *p_u, *p_v, *p_h, *p_wcat, *p_bcat, *p_den;
    cudaGetSymbolAddress((void**)&p_xlr,  g_xlr);
    cudaGetSymbolAddress((void**)&p_t,    g_t);
    cudaGetSymbolAddress((void**)&p_u,    g_u);
    cudaGetSymbolAddress((void**)&p_v,    g_v);
    cudaGetSymbolAddress((void**)&p_h,    g_h);
    cudaGetSymbolAddress((void**)&p_wcat, g_wcat);
    cudaGetSymbolAddress((void**)&p_bcat, g_bcat);
    cudaGetSymbolAddress((void**)&p_den,  g_den);

    // 0) weight concat + clear denominators + init h = bias_gat
    prep_wcat<<<(FDIM * 256 + 255) / 256, 256>>>(Wl, Wr, bl, br);
    cudaMemsetAsync(p_den, 0, (size_t)n * 8 * sizeof(float), 0);
    init_h<<<((size_t)n * FDIM + 255) / 256, 256>>>(bias_gat, n);

    const int MB = (n + 127) / 128;

    // 1) xlr = x @ [Wl|Wr] + [bl|br]
    sgemm<<<dim3(2, MB), 256>>>(x, p_wcat, p_xlr, p_bcat, n, 256, 128, 0);

    // 2) edge scores + softmax denominators
    int eblocks = (int)(((size_t)E * 32 + 255) / 256);
    edge_score<<<eblocks, 256>>>(ei, att, E);

    // 3) weighted aggregation into h
    edge_aggr<<<eblocks, 256>>>(ei, E);

    // 4) t = LN1(h)
    int lblocks = (n + 7) / 8;
    ln_kernel<<<lblocks, 256>>>(p_h, nullptr, g1, bn1, p_t, n);

    // 5) u = silu(t @ W1 + bW1)
    sgemm<<<dim3(4, MB), 256>>>(p_t, W1, p_u, bW1, n, 512, 128, 1);

    // 6) v = u @ W2 + bW2
    sgemm<<<dim3(1, MB), 256>>>(p_u, W2, p_v, bW2, n, 128, 512, 0);

    // 7) out = LN2(h + v)
    ln_kernel<<<lblocks, 256>>>(p_h, p_v, g2, bn2, out, n);
}

// round 2
// speedup vs baseline: 1.5278x; 1.5278x over previous
#include <cuda_runtime.h>
#include <cuda_bf16.h>
#include <math.h>

#define NMAX 100000
#define EMAX 1600000
#define FDIM 128
#define FFDIM 512

// ---------------- scratch (static device globals; no allocation) ----------------
__device__ float g_xlr[(size_t)NMAX * 256];   // [N, 256]: cols 0..127 = xl, 128..255 = xr
__device__ float g_h  [(size_t)NMAX * FDIM];  // GAT output (+bias), residual stream
__device__ float g_t  [(size_t)NMAX * FDIM];  // LN1 output
__device__ float g_u  [(size_t)NMAX * FFDIM]; // silu(t@W1+b)
__device__ float g_v  [(size_t)NMAX * FDIM];  // u@W2+b
__device__ float g_wcat[FDIM * 256];          // [Wl | Wr] concatenated along cols
__device__ float g_bcat[256];

// CSR build scratch
__device__ int g_deg [NMAX];
__device__ int g_off [NMAX];   // exclusive offsets
__device__ int g_cur [NMAX];   // scatter cursors
__device__ int g_inc [NMAX];   // per-block inclusive scan
__device__ int g_bsum[1024];   // block sums (needs ceil(100000/256)=391)
__device__ int g_srcs[EMAX];   // src ids sorted by dst

// ---------------- weight concat prep ----------------
__global__ void prep_wcat(const float* __restrict__ Wl, const float* __restrict__ Wr,
                          const float* __restrict__ bl, const float* __restrict__ br) {
    int i = blockIdx.x * blockDim.x + threadIdx.x;
    if (i < FDIM * 256) {
        int k = i >> 8, j = i & 255;
        g_wcat[i] = (j < 128) ? Wl[k * 128 + j] : Wr[k * 128 + (j - 128)];
    }
    if (i < 256) g_bcat[i] = (i < 128) ? bl[i] : br[i - 128];
}

// ---------------- CSR build ----------------
__global__ void k_hist(const int* __restrict__ ei, int E_) {
    int i = blockIdx.x * blockDim.x + threadIdx.x;
    if (i < E_) atomicAdd(&g_deg[ei[E_ + i]], 1);
}

// 2-level scan: per-block inclusive scan of 256 elements
__global__ void k_scan1(int n) {
    __shared__ int sm[256];
    int t = threadIdx.x;
    int idx = blockIdx.x * 256 + t;
    int v = (idx < n) ? g_deg[idx] : 0;
    sm[t] = v;
    __syncthreads();
#pragma unroll
    for (int o = 1; o < 256; o <<= 1) {
        int add = (t >= o) ? sm[t - o] : 0;
        __syncthreads();
        sm[t] += add;
        __syncthreads();
    }
    if (idx < n) g_inc[idx] = sm[t];
    if (t == 255) g_bsum[blockIdx.x] = sm[255];
}

__global__ void k_scan2(int nblocks) {
    __shared__ int sm[1024];
    int t = threadIdx.x;
    sm[t] = (t < nblocks) ? g_bsum[t] : 0;
    __syncthreads();
#pragma unroll
    for (int o = 1; o < 1024; o <<= 1) {
        int add = (t >= o) ? sm[t - o] : 0;
        __syncthreads();
        sm[t] += add;
        __syncthreads();
    }
    if (t < nblocks) g_bsum[t] = sm[t];   // inclusive block-sum scan
}

__global__ void k_scan3(int n) {
    int idx = blockIdx.x * blockDim.x + threadIdx.x;
    if (idx >= n) return;
    int b = idx >> 8;
    int prev = (b > 0) ? g_bsum[b - 1] : 0;
    int excl = g_inc[idx] - g_deg[idx] + prev;
    g_off[idx] = excl;
    g_cur[idx] = excl;
}

__global__ void k_scatter(const int* __restrict__ ei, int E_) {
    int i = blockIdx.x * blockDim.x + threadIdx.x;
    if (i >= E_) return;
    int dst = ei[E_ + i];
    int pos = atomicAdd(&g_cur[dst], 1);
    g_srcs[pos] = ei[i];
}

// ---------------- fused GAT gather: softmax + aggregation in one pass ----------------
// one warp per node; lane covers 4 channels (float4); head = lane>>2
__global__ void __launch_bounds__(256)
k_gather(const float* __restrict__ att, const float* __restrict__ bias, int n) {
    int warp = (blockIdx.x * blockDim.x + threadIdx.x) >> 5;
    int lane = threadIdx.x & 31;
    if (warp >= n) return;

    const float4* xlr4 = (const float4*)g_xlr;
    float4 xr = xlr4[(size_t)warp * 64 + 32 + lane];
    float4 w  = ((const float4*)att)[lane];

    int start = g_off[warp];
    int deg   = g_deg[warp];

    float4 ws = make_float4(0.f, 0.f, 0.f, 0.f);
    float den = 0.f;

#define EDGE_STEP(a)                                                           \
    {                                                                          \
        float4 t;                                                              \
        t.x = a.x + xr.x; t.x = t.x > 0.f ? t.x : 0.2f * t.x;                  \
        t.y = a.y + xr.y; t.y = t.y > 0.f ? t.y : 0.2f * t.y;                  \
        t.z = a.z + xr.z; t.z = t.z > 0.f ? t.z : 0.2f * t.z;                  \
        t.w = a.w + xr.w; t.w = t.w > 0.f ? t.w : 0.2f * t.w;                  \
        float p = t.x * w.x + t.y * w.y + t.z * w.z + t.w * w.w;               \
        p += __shfl_xor_sync(0xffffffffu, p, 1);                               \
        p += __shfl_xor_sync(0xffffffffu, p, 2);                               \
        float ex = expf(p);                                                    \
        den += ex;                                                             \
        ws.x += ex * a.x; ws.y += ex * a.y;                                    \
        ws.z += ex * a.z; ws.w += ex * a.w;                                    \
    }

    int j = 0;
    for (; j + 4 <= deg; j += 4) {
        int s0 = g_srcs[start + j + 0];
        int s1 = g_srcs[start + j + 1];
        int s2 = g_srcs[start + j + 2];
        int s3 = g_srcs[start + j + 3];
        float4 a0 = xlr4[(size_t)s0 * 64 + lane];
        float4 a1 = xlr4[(size_t)s1 * 64 + lane];
        float4 a2 = xlr4[(size_t)s2 * 64 + lane];
        float4 a3 = xlr4[(size_t)s3 * 64 + lane];
        EDGE_STEP(a0) EDGE_STEP(a1) EDGE_STEP(a2) EDGE_STEP(a3)
    }
    for (; j < deg; j++) {
        int s = g_srcs[start + j];
        float4 a = xlr4[(size_t)s * 64 + lane];
        EDGE_STEP(a)
    }
#undef EDGE_STEP

    float invd = (den > 0.f) ? (1.f / den) : 0.f;
    float4 bb = ((const float4*)bias)[lane];
    float4 o;
    o.x = ws.x * invd + bb.x;
    o.y = ws.y * invd + bb.y;
    o.z = ws.z * invd + bb.z;
    o.w = ws.w * invd + bb.w;
    ((float4*)(g_h + (size_t)warp * 128))[lane] = o;
}

// ---------------- SGEMM: C[M,N] = A[M,K] @ B[K,N] + bias, optional silu ----------------
__global__ void __launch_bounds__(256, 2)
sgemm(const float* __restrict__ A, const float* __restrict__ Bm,
      float* __restrict__ C, const float* __restrict__ bias,
      int M, int N, int K, int act) {
    __shared__ float As[8][128];
    __shared__ float Bs[8][128];
    const int tid  = threadIdx.x;
    const int brow = blockIdx.y * 128;
    const int bcol = blockIdx.x * 128;

    const int a_row = tid >> 1;
    const int a_col = (tid & 1) << 2;
    const int b_row = tid >> 5;
    const int b_col = (tid & 31) << 2;

    const int ty = (tid >> 4) << 3;
    const int tx = (tid & 15) << 3;

    float acc[8][8];
#pragma unroll
    for (int i = 0; i < 8; i++)
#pragma unroll
        for (int j = 0; j < 8; j++) acc[i][j] = 0.f;

    const int grow = brow + a_row;
    const bool a_valid = (grow < M);
    const float* Aptr = A + (size_t)grow * K + a_col;

    for (int k0 = 0; k0 < K; k0 += 8) {
        float4 a4 = a_valid ? *(const float4*)(Aptr + k0) : make_float4(0.f, 0.f, 0.f, 0.f);
        As[a_col + 0][a_row] = a4.x;
        As[a_col + 1][a_row] = a4.y;
        As[a_col + 2][a_row] = a4.z;
        As[a_col + 3][a_row] = a4.w;
        *(float4*)&Bs[b_row][b_col] =
            *(const float4*)(Bm + (size_t)(k0 + b_row) * N + bcol + b_col);
        __syncthreads();
#pragma unroll
        for (int k = 0; k < 8; k++) {
            float4 a0 = *(const float4*)&As[k][ty];
            float4 a1 = *(const float4*)&As[k][ty + 4];
            float4 b0 = *(const float4*)&Bs[k][tx];
            float4 b1 = *(const float4*)&Bs[k][tx + 4];
            float ar[8] = {a0.x, a0.y, a0.z, a0.w, a1.x, a1.y, a1.z, a1.w};
            float br_[8] = {b0.x, b0.y, b0.z, b0.w, b1.x, b1.y, b1.z, b1.w};
#pragma unroll
            for (int i = 0; i < 8; i++)
#pragma unroll
                for (int j = 0; j < 8; j++) acc[i][j] += ar[i] * br_[j];
        }
        __syncthreads();
    }

#pragma unroll
    for (int i = 0; i < 8; i++) {
        int row = brow + ty + i;
        if (row >= M) continue;
        float out[8];
#pragma unroll
        for (int j = 0; j < 8; j++) {
            float c = acc[i][j] + bias[bcol + tx + j];
            if (act) c = c / (1.f + expf(-c));   // silu
            out[j] = c;
        }
        float* crow = C + (size_t)row * N + bcol + tx;
        *(float4*)(crow)     = make_float4(out[0], out[1], out[2], out[3]);
        *(float4*)(crow + 4) = make_float4(out[4], out[5], out[6], out[7]);
    }
}

// ---------------- LayerNorm (warp per node); optional residual add ----------------
__global__ void ln_kernel(const float* __restrict__ in, const float* __restrict__ res,
                          const float* __restrict__ g, const float* __restrict__ b,
                          float* __restrict__ out, int n) {
    int warp = (blockIdx.x * blockDim.x + threadIdx.x) >> 5;
    int lane = threadIdx.x & 31;
    if (warp >= n) return;
    float4 v = ((const float4*)(in + (size_t)warp * 128))[lane];
    if (res) {
        float4 r = ((const float4*)(res + (size_t)warp * 128))[lane];
        v.x += r.x; v.y += r.y; v.z += r.z; v.w += r.w;
    }
    float s  = v.x + v.y + v.z + v.w;
    float sq = v.x * v.x + v.y * v.y + v.z * v.z + v.w * v.w;
#pragma unroll
    for (int o = 16; o; o >>= 1) {
        s  += __shfl_xor_sync(0xffffffffu, s, o);
        sq += __shfl_xor_sync(0xffffffffu, sq, o);
    }
    float mu = s * (1.f / 128.f);
    float var = sq * (1.f / 128.f) - mu * mu;
    float rstd = rsqrtf(var + 1e-5f);
    float4 gg = ((const float4*)g)[lane];
    float4 bb = ((const float4*)b)[lane];
    float4 o4;
    o4.x = (v.x - mu) * rstd * gg.x + bb.x;
    o4.y = (v.y - mu) * rstd * gg.y + bb.y;
    o4.z = (v.z - mu) * rstd * gg.z + bb.z;
    o4.w = (v.w - mu) * rstd * gg.w + bb.w;
    ((float4*)(out + (size_t)warp * 128))[lane] = o4;
}

// ---------------- launch ----------------
extern "C" void kernel_launch(void* const* d_in, const int* in_sizes, int n_in,
                              void* d_out, int out_size) {
    const float* x        = (const float*)d_in[0];
    const int*   ei       = (const int*)  d_in[1];
    const float* Wl       = (const float*)d_in[2];
    const float* bl       = (const float*)d_in[3];
    const float* Wr       = (const float*)d_in[4];
    const float* br       = (const float*)d_in[5];
    const float* att      = (const float*)d_in[6];
    const float* bias_gat = (const float*)d_in[7];
    const float* g1       = (const float*)d_in[8];
    const float* bn1      = (const float*)d_in[9];
    const float* W1       = (const float*)d_in[10];
    const float* bW1      = (const float*)d_in[11];
    const float* W2       = (const float*)d_in[12];
    const float* bW2      = (const float*)d_in[13];
    const float* g2       = (const float*)d_in[14];
    const float* bn2      = (const float*)d_in[15];
    float* out = (float*)d_out;

    const int n = in_sizes[0] / FDIM;      // 100000
    const int E = in_sizes[1] / 2;         // 1600000

    float *p_xlr, *p_t, *p_u, *p_v, *p_h, *p_wcat, *p_bcat;
    int *p_deg;
    cudaGetSymbolAddress((void**)&p_xlr,  g_xlr);
    cudaGetSymbolAddress((void**)&p_t,    g_t);
    cudaGetSymbolAddress((void**)&p_u,    g_u);
    cudaGetSymbolAddress((void**)&p_v,    g_v);
    cudaGetSymbolAddress((void**)&p_h,    g_h);
    cudaGetSymbolAddress((void**)&p_wcat, g_wcat);
    cudaGetSymbolAddress((void**)&p_bcat, g_bcat);
    cudaGetSymbolAddress((void**)&p_deg,  g_deg);

    const int scan_blocks = (n + 255) / 256;   // 391

    // 0) weight concat + zero degree histogram
    prep_wcat<<<(FDIM * 256 + 255) / 256, 256>>>(Wl, Wr, bl, br);
    cudaMemsetAsync(p_deg, 0, (size_t)n * sizeof(int), 0);

    // 1) CSR build: histogram -> scan -> scatter
    k_hist<<<(E + 255) / 256, 256>>>(ei, E);
    k_scan1<<<scan_blocks, 256>>>(n);
    k_scan2<<<1, 1024>>>(scan_blocks);
    k_scan3<<<scan_blocks, 256>>>(n);
    k_scatter<<<(E + 255) / 256, 256>>>(ei, E);

    const int MB = (n + 127) / 128;

    // 2) xlr = x @ [Wl|Wr] + [bl|br]   (overlaps nothing, but ordered fine)
    sgemm<<<dim3(2, MB), 256>>>(x, p_wcat, p_xlr, p_bcat, n, 256, 128, 0);

    // 3) fused GAT: per-node gather, softmax + aggregation + bias
    k_gather<<<(n + 7) / 8, 256>>>(att, bias_gat, n);

    // 4) t = LN1(h)
    int lblocks = (n + 7) / 8;
    ln_kernel<<<lblocks, 256>>>(p_h, nullptr, g1, bn1, p_t, n);

    // 5) u = silu(t @ W1 + bW1)
    sgemm<<<dim3(4, MB), 256>>>(p_t, W1, p_u, bW1, n, 512, 128, 1);

    // 6) v = u @ W2 + bW2
    sgemm<<<dim3(1, MB), 256>>>(p_u, W2, p_v, bW2, n, 128, 512, 0);

    // 7) out = LN2(h + v)
    ln_kernel<<<lblocks, 256>>>(p_h, p_v, g2, bn2, out, n);
}

// round 3
// speedup vs baseline: 2.5450x; 1.6658x over previous
#include <cuda_runtime.h>
#include <cuda_bf16.h>
#include <math.h>

#define NMAX 100000
#define EMAX 1600000
#define FDIM 128
#define FFDIM 512

// ---------------- scratch (static device globals; no allocation) ----------------
__device__ float g_xlr[(size_t)NMAX * 256];   // [N, 256]: cols 0..127 = xl, 128..255 = xr
__device__ float g_h  [(size_t)NMAX * FDIM];  // GAT output (+bias), residual stream
__device__ float g_t  [(size_t)NMAX * FDIM];  // LN1 output
__device__ float g_u  [(size_t)NMAX * FFDIM]; // silu(t@W1+b)
__device__ float g_v  [(size_t)NMAX * FDIM];  // u@W2+b
__device__ float g_wcat[FDIM * 256];          // [Wl | Wr] concatenated along cols
__device__ float g_bcat[256];

// CSR build scratch
__device__ int g_deg [NMAX];
__device__ int g_off [NMAX];
__device__ int g_cur [NMAX];
__device__ int g_inc [NMAX];
__device__ int g_bsum[1024];
__device__ int g_srcs[EMAX];

// ---------------- weight concat prep ----------------
__global__ void prep_wcat(const float* __restrict__ Wl, const float* __restrict__ Wr,
                          const float* __restrict__ bl, const float* __restrict__ br) {
    int i = blockIdx.x * blockDim.x + threadIdx.x;
    if (i < FDIM * 256) {
        int k = i >> 8, j = i & 255;
        g_wcat[i] = (j < 128) ? Wl[k * 128 + j] : Wr[k * 128 + (j - 128)];
    }
    if (i < 256) g_bcat[i] = (i < 128) ? bl[i] : br[i - 128];
}

// ---------------- CSR build ----------------
__global__ void k_hist(const int* __restrict__ ei, int E_) {
    int i = blockIdx.x * blockDim.x + threadIdx.x;
    if (i < E_) atomicAdd(&g_deg[ei[E_ + i]], 1);
}

__global__ void k_scan1(int n) {
    __shared__ int sm[256];
    int t = threadIdx.x;
    int idx = blockIdx.x * 256 + t;
    int v = (idx < n) ? g_deg[idx] : 0;
    sm[t] = v;
    __syncthreads();
#pragma unroll
    for (int o = 1; o < 256; o <<= 1) {
        int add = (t >= o) ? sm[t - o] : 0;
        __syncthreads();
        sm[t] += add;
        __syncthreads();
    }
    if (idx < n) g_inc[idx] = sm[t];
    if (t == 255) g_bsum[blockIdx.x] = sm[255];
}

__global__ void k_scan2(int nblocks) {
    __shared__ int sm[1024];
    int t = threadIdx.x;
    sm[t] = (t < nblocks) ? g_bsum[t] : 0;
    __syncthreads();
#pragma unroll
    for (int o = 1; o < 1024; o <<= 1) {
        int add = (t >= o) ? sm[t - o] : 0;
        __syncthreads();
        sm[t] += add;
        __syncthreads();
    }
    if (t < nblocks) g_bsum[t] = sm[t];
}

__global__ void k_scan3(int n) {
    int idx = blockIdx.x * blockDim.x + threadIdx.x;
    if (idx >= n) return;
    int b = idx >> 8;
    int prev = (b > 0) ? g_bsum[b - 1] : 0;
    int excl = g_inc[idx] - g_deg[idx] + prev;
    g_off[idx] = excl;
    g_cur[idx] = excl;
}

__global__ void k_scatter(const int* __restrict__ ei, int E_) {
    int i = blockIdx.x * blockDim.x + threadIdx.x;
    if (i >= E_) return;
    int dst = ei[E_ + i];
    int pos = atomicAdd(&g_cur[dst], 1);
    g_srcs[pos] = ei[i];
}

// ---------------- fused GAT gather ----------------
__global__ void __launch_bounds__(256)
k_gather(const float* __restrict__ att, const float* __restrict__ bias, int n) {
    int warp = (blockIdx.x * blockDim.x + threadIdx.x) >> 5;
    int lane = threadIdx.x & 31;
    if (warp >= n) return;

    const float4* xlr4 = (const float4*)g_xlr;
    float4 xr = xlr4[(size_t)warp * 64 + 32 + lane];
    float4 w  = ((const float4*)att)[lane];

    int start = g_off[warp];
    int deg   = g_deg[warp];

    float4 ws = make_float4(0.f, 0.f, 0.f, 0.f);
    float den = 0.f;

#define EDGE_STEP(a)                                                           \
    {                                                                          \
        float4 t;                                                              \
        t.x = a.x + xr.x; t.x = t.x > 0.f ? t.x : 0.2f * t.x;                  \
        t.y = a.y + xr.y; t.y = t.y > 0.f ? t.y : 0.2f * t.y;                  \
        t.z = a.z + xr.z; t.z = t.z > 0.f ? t.z : 0.2f * t.z;                  \
        t.w = a.w + xr.w; t.w = t.w > 0.f ? t.w : 0.2f * t.w;                  \
        float p = t.x * w.x + t.y * w.y + t.z * w.z + t.w * w.w;               \
        p += __shfl_xor_sync(0xffffffffu, p, 1);                               \
        p += __shfl_xor_sync(0xffffffffu, p, 2);                               \
        float ex = expf(p);                                                    \
        den += ex;                                                             \
        ws.x += ex * a.x; ws.y += ex * a.y;                                    \
        ws.z += ex * a.z; ws.w += ex * a.w;                                    \
    }

    int j = 0;
    for (; j + 4 <= deg; j += 4) {
        int s0 = g_srcs[start + j + 0];
        int s1 = g_srcs[start + j + 1];
        int s2 = g_srcs[start + j + 2];
        int s3 = g_srcs[start + j + 3];
        float4 a0 = xlr4[(size_t)s0 * 64 + lane];
        float4 a1 = xlr4[(size_t)s1 * 64 + lane];
        float4 a2 = xlr4[(size_t)s2 * 64 + lane];
        float4 a3 = xlr4[(size_t)s3 * 64 + lane];
        EDGE_STEP(a0) EDGE_STEP(a1) EDGE_STEP(a2) EDGE_STEP(a3)
    }
    for (; j < deg; j++) {
        int s = g_srcs[start + j];
        float4 a = xlr4[(size_t)s * 64 + lane];
        EDGE_STEP(a)
    }
#undef EDGE_STEP

    float invd = (den > 0.f) ? (1.f / den) : 0.f;
    float4 bb = ((const float4*)bias)[lane];
    float4 o;
    o.x = ws.x * invd + bb.x;
    o.y = ws.y * invd + bb.y;
    o.z = ws.z * invd + bb.z;
    o.w = ws.w * invd + bb.w;
    ((float4*)(g_h + (size_t)warp * 128))[lane] = o;
}

// ---------------- fp32 SGEMM (kept for x@Wcat, exact attention path) ----------------
__global__ void __launch_bounds__(256, 2)
sgemm(const float* __restrict__ A, const float* __restrict__ Bm,
      float* __restrict__ C, const float* __restrict__ bias,
      int M, int N, int K, int act) {
    __shared__ float As[8][128];
    __shared__ float Bs[8][128];
    const int tid  = threadIdx.x;
    const int brow = blockIdx.y * 128;
    const int bcol = blockIdx.x * 128;

    const int a_row = tid >> 1;
    const int a_col = (tid & 1) << 2;
    const int b_row = tid >> 5;
    const int b_col = (tid & 31) << 2;

    const int ty = (tid >> 4) << 3;
    const int tx = (tid & 15) << 3;

    float acc[8][8];
#pragma unroll
    for (int i = 0; i < 8; i++)
#pragma unroll
        for (int j = 0; j < 8; j++) acc[i][j] = 0.f;

    const int grow = brow + a_row;
    const bool a_valid = (grow < M);
    const float* Aptr = A + (size_t)grow * K + a_col;

    for (int k0 = 0; k0 < K; k0 += 8) {
        float4 a4 = a_valid ? *(const float4*)(Aptr + k0) : make_float4(0.f, 0.f, 0.f, 0.f);
        As[a_col + 0][a_row] = a4.x;
        As[a_col + 1][a_row] = a4.y;
        As[a_col + 2][a_row] = a4.z;
        As[a_col + 3][a_row] = a4.w;
        *(float4*)&Bs[b_row][b_col] =
            *(const float4*)(Bm + (size_t)(k0 + b_row) * N + bcol + b_col);
        __syncthreads();
#pragma unroll
        for (int k = 0; k < 8; k++) {
            float4 a0 = *(const float4*)&As[k][ty];
            float4 a1 = *(const float4*)&As[k][ty + 4];
            float4 b0 = *(const float4*)&Bs[k][tx];
            float4 b1 = *(const float4*)&Bs[k][tx + 4];
            float ar[8] = {a0.x, a0.y, a0.z, a0.w, a1.x, a1.y, a1.z, a1.w};
            float br_[8] = {b0.x, b0.y, b0.z, b0.w, b1.x, b1.y, b1.z, b1.w};
#pragma unroll
            for (int i = 0; i < 8; i++)
#pragma unroll
                for (int j = 0; j < 8; j++) acc[i][j] += ar[i] * br_[j];
        }
        __syncthreads();
    }

#pragma unroll
    for (int i = 0; i < 8; i++) {
        int row = brow + ty + i;
        if (row >= M) continue;
        float out[8];
#pragma unroll
        for (int j = 0; j < 8; j++) {
            float c = acc[i][j] + bias[bcol + tx + j];
            if (act) c = c / (1.f + expf(-c));
            out[j] = c;
        }
        float* crow = C + (size_t)row * N + bcol + tx;
        *(float4*)(crow)     = make_float4(out[0], out[1], out[2], out[3]);
        *(float4*)(crow + 4) = make_float4(out[4], out[5], out[6], out[7]);
    }
}

// ---------------- TF32 tensor-core GEMM (FFN) ----------------
__device__ __forceinline__ unsigned f2tf32(float f) {
    unsigned r;
    asm("cvt.rna.tf32.f32 %0, %1;" : "=r"(r) : "f"(f));
    return r;
}

// C[M,N] = A[M,K] @ B[K,N] + bias, optional silu. BM=128, BN=128, BK=32.
// 8 warps, each owns a 32x64 warp tile (2 m16 x 8 n8 MMAs per k8 step).
__global__ void __launch_bounds__(256, 2)
mma_gemm(const float* __restrict__ A, const float* __restrict__ Bm,
         float* __restrict__ C, const float* __restrict__ bias,
         int M, int N, int K, int act) {
    __shared__ unsigned As[128][36];   // [m][k], stride 36 => conflict-free frags
    __shared__ unsigned Bs[32][136];   // [k][n], stride 136 => conflict-free frags

    const int tid  = threadIdx.x;
    const int warp = tid >> 5;
    const int lane = tid & 31;
    const int wm   = (warp >> 1) * 32;   // 4 warps along M
    const int wn   = (warp & 1) * 64;    // 2 warps along N
    const int g    = lane >> 2;          // 0..7
    const int tg   = lane & 3;           // 0..3
    const int brow = blockIdx.y * 128;
    const int bcol = blockIdx.x * 128;

    float acc[2][8][4];
#pragma unroll
    for (int i = 0; i < 2; i++)
#pragma unroll
        for (int j = 0; j < 8; j++)
#pragma unroll
            for (int q = 0; q < 4; q++) acc[i][j][q] = 0.f;

    const int arow   = tid >> 3;          // 0..31
    const int acol   = (tid & 7) * 4;     // 0..28
    const int brow_l = tid >> 5;          // 0..7
    const int bcol_l = (tid & 31) * 4;    // 0..124

    for (int k0 = 0; k0 < K; k0 += 32) {
#pragma unroll
        for (int i = 0; i < 4; i++) {
            int r = arow + i * 32;
            int grow = brow + r;
            float4 v = (grow < M) ? *(const float4*)(A + (size_t)grow * K + k0 + acol)
                                  : make_float4(0.f, 0.f, 0.f, 0.f);
            As[r][acol + 0] = f2tf32(v.x);
            As[r][acol + 1] = f2tf32(v.y);
            As[r][acol + 2] = f2tf32(v.z);
            As[r][acol + 3] = f2tf32(v.w);
        }
#pragma unroll
        for (int i = 0; i < 4; i++) {
            int r = brow_l + i * 8;
            float4 v = *(const float4*)(Bm + (size_t)(k0 + r) * N + bcol + bcol_l);
            Bs[r][bcol_l + 0] = f2tf32(v.x);
            Bs[r][bcol_l + 1] = f2tf32(v.y);
            Bs[r][bcol_l + 2] = f2tf32(v.z);
            Bs[r][bcol_l + 3] = f2tf32(v.w);
        }
        __syncthreads();

#pragma unroll
        for (int ks = 0; ks < 4; ks++) {
            const int kk = ks * 8;
            unsigned a[2][4], b[8][2];
#pragma unroll
            for (int mt = 0; mt < 2; mt++) {
                int rm = wm + mt * 16 + g;
                a[mt][0] = As[rm][kk + tg];
                a[mt][1] = As[rm + 8][kk + tg];
                a[mt][2] = As[rm][kk + tg + 4];
                a[mt][3] = As[rm + 8][kk + tg + 4];
            }
#pragma unroll
            for (int nt = 0; nt < 8; nt++) {
                int cn = wn + nt * 8 + g;
                b[nt][0] = Bs[kk + tg][cn];
                b[nt][1] = Bs[kk + tg + 4][cn];
            }
#pragma unroll
            for (int mt = 0; mt < 2; mt++)
#pragma unroll
                for (int nt = 0; nt < 8; nt++) {
                    asm volatile(
                        "mma.sync.aligned.m16n8k8.row.col.f32.tf32.tf32.f32 "
                        "{%0,%1,%2,%3}, {%4,%5,%6,%7}, {%8,%9}, {%0,%1,%2,%3};\n"
                        : "+f"(acc[mt][nt][0]), "+f"(acc[mt][nt][1]),
                          "+f"(acc[mt][nt][2]), "+f"(acc[mt][nt][3])
                        : "r"(a[mt][0]), "r"(a[mt][1]), "r"(a[mt][2]), "r"(a[mt][3]),
                          "r"(b[nt][0]), "r"(b[nt][1]));
                }
        }
        __syncthreads();
    }

    // epilogue: c0:(g,2tg) c1:(g,2tg+1) c2:(g+8,2tg) c3:(g+8,2tg+1)
#pragma unroll
    for (int mt = 0; mt < 2; mt++) {
        int r0 = brow + wm + mt * 16 + g;
        int r1 = r0 + 8;
#pragma unroll
        for (int nt = 0; nt < 8; nt++) {
            int c = bcol + wn + nt * 8 + 2 * tg;
            float b0 = bias[c], b1 = bias[c + 1];
            float v00 = acc[mt][nt][0] + b0;
            float v01 = acc[mt][nt][1] + b1;
            float v10 = acc[mt][nt][2] + b0;
            float v11 = acc[mt][nt][3] + b1;
            if (act) {
                v00 = v00 / (1.f + expf(-v00));
                v01 = v01 / (1.f + expf(-v01));
                v10 = v10 / (1.f + expf(-v10));
                v11 = v11 / (1.f + expf(-v11));
            }
            if (r0 < M) *(float2*)(C + (size_t)r0 * N + c) = make_float2(v00, v01);
            if (r1 < M) *(float2*)(C + (size_t)r1 * N + c) = make_float2(v10, v11);
        }
    }
}

// ---------------- LayerNorm (warp per node); optional residual add ----------------
__global__ void ln_kernel(const float* __restrict__ in, const float* __restrict__ res,
                          const float* __restrict__ g, const float* __restrict__ b,
                          float* __restrict__ out, int n) {
    int warp = (blockIdx.x * blockDim.x + threadIdx.x) >> 5;
    int lane = threadIdx.x & 31;
    if (warp >= n) return;
    float4 v = ((const float4*)(in + (size_t)warp * 128))[lane];
    if (res) {
        float4 r = ((const float4*)(res + (size_t)warp * 128))[lane];
        v.x += r.x; v.y += r.y; v.z += r.z; v.w += r.w;
    }
    float s  = v.x + v.y + v.z + v.w;
    float sq = v.x * v.x + v.y * v.y + v.z * v.z + v.w * v.w;
#pragma unroll
    for (int o = 16; o; o >>= 1) {
        s  += __shfl_xor_sync(0xffffffffu, s, o);
        sq += __shfl_xor_sync(0xffffffffu, sq, o);
    }
    float mu = s * (1.f / 128.f);
    float var = sq * (1.f / 128.f) - mu * mu;
    float rstd = rsqrtf(var + 1e-5f);
    float4 gg = ((const float4*)g)[lane];
    float4 bb = ((const float4*)b)[lane];
    float4 o4;
    o4.x = (v.x - mu) * rstd * gg.x + bb.x;
    o4.y = (v.y - mu) * rstd * gg.y + bb.y;
    o4.z = (v.z - mu) * rstd * gg.z + bb.z;
    o4.w = (v.w - mu) * rstd * gg.w + bb.w;
    ((float4*)(out + (size_t)warp * 128))[lane] = o4;
}

// ---------------- launch ----------------
extern "C" void kernel_launch(void* const* d_in, const int* in_sizes, int n_in,
                              void* d_out, int out_size) {
    const float* x        = (const float*)d_in[0];
    const int*   ei       = (const int*)  d_in[1];
    const float* Wl       = (const float*)d_in[2];
    const float* bl       = (const float*)d_in[3];
    const float* Wr       = (const float*)d_in[4];
    const float* br       = (const float*)d_in[5];
    const float* att      = (const float*)d_in[6];
    const float* bias_gat = (const float*)d_in[7];
    const float* g1       = (const float*)d_in[8];
    const float* bn1      = (const float*)d_in[9];
    const float* W1       = (const float*)d_in[10];
    const float* bW1      = (const float*)d_in[11];
    const float* W2       = (const float*)d_in[12];
    const float* bW2      = (const float*)d_in[13];
    const float* g2       = (const float*)d_in[14];
    const float* bn2      = (const float*)d_in[15];
    float* out = (float*)d_out;

    const int n = in_sizes[0] / FDIM;      // 100000
    const int E = in_sizes[1] / 2;         // 1600000

    float *p_xlr, *p_t, *p_u, *p_v, *p_h, *p_wcat, *p_bcat;
    int *p_deg;
    cudaGetSymbolAddress((void**)&p_xlr,  g_xlr);
    cudaGetSymbolAddress((void**)&p_t,    g_t);
    cudaGetSymbolAddress((void**)&p_u,    g_u);
    cudaGetSymbolAddress((void**)&p_v,    g_v);
    cudaGetSymbolAddress((void**)&p_h,    g_h);
    cudaGetSymbolAddress((void**)&p_wcat, g_wcat);
    cudaGetSymbolAddress((void**)&p_bcat, g_bcat);
    cudaGetSymbolAddress((void**)&p_deg,  g_deg);

    const int scan_blocks = (n + 255) / 256;

    prep_wcat<<<(FDIM * 256 + 255) / 256, 256>>>(Wl, Wr, bl, br);
    cudaMemsetAsync(p_deg, 0, (size_t)n * sizeof(int), 0);

    k_hist<<<(E + 255) / 256, 256>>>(ei, E);
    k_scan1<<<scan_blocks, 256>>>(n);
    k_scan2<<<1, 1024>>>(scan_blocks);
    k_scan3<<<scan_blocks, 256>>>(n);
    k_scatter<<<(E + 255) / 256, 256>>>(ei, E);

    const int MB = (n + 127) / 128;

    // 1) xlr = x @ [Wl|Wr] + [bl|br]   (fp32 -> exact attention inputs)
    sgemm<<<dim3(2, MB), 256>>>(x, p_wcat, p_xlr, p_bcat, n, 256, 128, 0);

    // 2) fused GAT gather
    k_gather<<<(n + 7) / 8, 256>>>(att, bias_gat, n);

    // 3) t = LN1(h)
    int lblocks = (n + 7) / 8;
    ln_kernel<<<lblocks, 256>>>(p_h, nullptr, g1, bn1, p_t, n);

    // 4) u = silu(t @ W1 + bW1)  -- tf32 tensor cores
    mma_gemm<<<dim3(4, MB), 256>>>(p_t, W1, p_u, bW1, n, 512, 128, 1);

    // 5) v = u @ W2 + bW2        -- tf32 tensor cores
    mma_gemm<<<dim3(1, MB), 256>>>(p_u, W2, p_v, bW2, n, 128, 512, 0);

    // 6) out = LN2(h + v)
    ln_kernel<<<lblocks, 256>>>(p_h, p_v, g2, bn2, out, n);
}

// round 4
// speedup vs baseline: 3.1646x; 1.2435x over previous
#include <cuda_runtime.h>
#include <cuda_bf16.h>
#include <math.h>

#define NMAX 100000
#define EMAX 1600000
#define FDIM 128
#define FFDIM 512

// ---------------- scratch (static device globals; no allocation) ----------------
__device__ float g_xl [(size_t)NMAX * FDIM];  // source-side transform (gathered)
__device__ float g_xr [(size_t)NMAX * FDIM];  // target-side transform
__device__ float g_h  [(size_t)NMAX * FDIM];  // GAT output (+bias), residual stream
__device__ float g_t  [(size_t)NMAX * FDIM];  // LN1 output
__device__ float g_u  [(size_t)NMAX * FFDIM]; // silu(t@W1+b)
__device__ float g_v  [(size_t)NMAX * FDIM];  // u@W2+b
__device__ float g_wcat[FDIM * 256];          // [Wl | Wr] concatenated along cols
__device__ float g_bcat[256];

// CSR build scratch
__device__ int g_deg [NMAX];
__device__ int g_off [NMAX];
__device__ int g_cur [NMAX];
__device__ int g_inc [NMAX];
__device__ int g_bsum[1024];
__device__ int g_srcs[EMAX];

// ---------------- weight concat prep ----------------
__global__ void prep_wcat(const float* __restrict__ Wl, const float* __restrict__ Wr,
                          const float* __restrict__ bl, const float* __restrict__ br) {
    int i = blockIdx.x * blockDim.x + threadIdx.x;
    if (i < FDIM * 256) {
        int k = i >> 8, j = i & 255;
        g_wcat[i] = (j < 128) ? Wl[k * 128 + j] : Wr[k * 128 + (j - 128)];
    }
    if (i < 256) g_bcat[i] = (i < 128) ? bl[i] : br[i - 128];
}

// ---------------- CSR build ----------------
__global__ void k_hist(const int* __restrict__ ei, int E_) {
    int i = blockIdx.x * blockDim.x + threadIdx.x;
    if (i < E_) atomicAdd(&g_deg[ei[E_ + i]], 1);
}

__global__ void k_scan1(int n) {
    __shared__ int sm[256];
    int t = threadIdx.x;
    int idx = blockIdx.x * 256 + t;
    int v = (idx < n) ? g_deg[idx] : 0;
    sm[t] = v;
    __syncthreads();
#pragma unroll
    for (int o = 1; o < 256; o <<= 1) {
        int add = (t >= o) ? sm[t - o] : 0;
        __syncthreads();
        sm[t] += add;
        __syncthreads();
    }
    if (idx < n) g_inc[idx] = sm[t];
    if (t == 255) g_bsum[blockIdx.x] = sm[255];
}

__global__ void k_scan2(int nblocks) {
    __shared__ int sm[1024];
    int t = threadIdx.x;
    sm[t] = (t < nblocks) ? g_bsum[t] : 0;
    __syncthreads();
#pragma unroll
    for (int o = 1; o < 1024; o <<= 1) {
        int add = (t >= o) ? sm[t - o] : 0;
        __syncthreads();
        sm[t] += add;
        __syncthreads();
    }
    if (t < nblocks) g_bsum[t] = sm[t];
}

__global__ void k_scan3(int n) {
    int idx = blockIdx.x * blockDim.x + threadIdx.x;
    if (idx >= n) return;
    int b = idx >> 8;
    int prev = (b > 0) ? g_bsum[b - 1] : 0;
    int excl = g_inc[idx] - g_deg[idx] + prev;
    g_off[idx] = excl;
    g_cur[idx] = excl;
}

__global__ void k_scatter(const int* __restrict__ ei, int E_) {
    int i = blockIdx.x * blockDim.x + threadIdx.x;
    if (i >= E_) return;
    int dst = ei[E_ + i];
    int pos = atomicAdd(&g_cur[dst], 1);
    g_srcs[pos] = ei[i];
}

// ---------------- fused GAT gather + LayerNorm1 ----------------
// one warp per node; lane covers 4 channels (float4); head = lane>>2
__global__ void __launch_bounds__(256)
k_gather_ln(const float* __restrict__ att, const float* __restrict__ bias,
            const float* __restrict__ g1, const float* __restrict__ bn1, int n) {
    int warp = (blockIdx.x * blockDim.x + threadIdx.x) >> 5;
    int lane = threadIdx.x & 31;
    if (warp >= n) return;

    const float4* xl4 = (const float4*)g_xl;
    float4 xr = ((const float4*)g_xr)[(size_t)warp * 32 + lane];
    float4 w  = ((const float4*)att)[lane];

    int start = g_off[warp];
    int deg   = g_deg[warp];

    float4 ws = make_float4(0.f, 0.f, 0.f, 0.f);
    float den = 0.f;

#define EDGE_STEP(a)                                                           \
    {                                                                          \
        float4 t;                                                              \
        t.x = a.x + xr.x; t.x = t.x > 0.f ? t.x : 0.2f * t.x;                  \
        t.y = a.y + xr.y; t.y = t.y > 0.f ? t.y : 0.2f * t.y;                  \
        t.z = a.z + xr.z; t.z = t.z > 0.f ? t.z : 0.2f * t.z;                  \
        t.w = a.w + xr.w; t.w = t.w > 0.f ? t.w : 0.2f * t.w;                  \
        float p = t.x * w.x + t.y * w.y + t.z * w.z + t.w * w.w;               \
        p += __shfl_xor_sync(0xffffffffu, p, 1);                               \
        p += __shfl_xor_sync(0xffffffffu, p, 2);                               \
        float ex = expf(p);                                                    \
        den += ex;                                                             \
        ws.x += ex * a.x; ws.y += ex * a.y;                                    \
        ws.z += ex * a.z; ws.w += ex * a.w;                                    \
    }

    int j = 0;
    for (; j + 4 <= deg; j += 4) {
        int s0 = g_srcs[start + j + 0];
        int s1 = g_srcs[start + j + 1];
        int s2 = g_srcs[start + j + 2];
        int s3 = g_srcs[start + j + 3];
        float4 a0 = xl4[(size_t)s0 * 32 + lane];
        float4 a1 = xl4[(size_t)s1 * 32 + lane];
        float4 a2 = xl4[(size_t)s2 * 32 + lane];
        float4 a3 = xl4[(size_t)s3 * 32 + lane];
        EDGE_STEP(a0) EDGE_STEP(a1) EDGE_STEP(a2) EDGE_STEP(a3)
    }
    for (; j < deg; j++) {
        int s = g_srcs[start + j];
        float4 a = xl4[(size_t)s * 32 + lane];
        EDGE_STEP(a)
    }
#undef EDGE_STEP

    float invd = (den > 0.f) ? (1.f / den) : 0.f;
    float4 bb = ((const float4*)bias)[lane];
    float4 o;
    o.x = ws.x * invd + bb.x;
    o.y = ws.y * invd + bb.y;
    o.z = ws.z * invd + bb.z;
    o.w = ws.w * invd + bb.w;
    ((float4*)(g_h + (size_t)warp * 128))[lane] = o;

    // fused LayerNorm1 -> g_t
    float s  = o.x + o.y + o.z + o.w;
    float sq = o.x * o.x + o.y * o.y + o.z * o.z + o.w * o.w;
#pragma unroll
    for (int of = 16; of; of >>= 1) {
        s  += __shfl_xor_sync(0xffffffffu, s, of);
        sq += __shfl_xor_sync(0xffffffffu, sq, of);
    }
    float mu = s * (1.f / 128.f);
    float var = sq * (1.f / 128.f) - mu * mu;
    float rstd = rsqrtf(var + 1e-5f);
    float4 gg = ((const float4*)g1)[lane];
    float4 b1 = ((const float4*)bn1)[lane];
    float4 t4;
    t4.x = (o.x - mu) * rstd * gg.x + b1.x;
    t4.y = (o.y - mu) * rstd * gg.y + b1.y;
    t4.z = (o.z - mu) * rstd * gg.z + b1.z;
    t4.w = (o.w - mu) * rstd * gg.w + b1.w;
    ((float4*)(g_t + (size_t)warp * 128))[lane] = t4;
}

// ---------------- TF32 tensor-core GEMM ----------------
__device__ __forceinline__ unsigned f2tf32(float f) {
    unsigned r;
    asm("cvt.rna.tf32.f32 %0, %1;" : "=r"(r) : "f"(f));
    return r;
}

// C[M,N] = A[M,K] @ B[K,N] + bias, optional silu. BM=128, BN=128, BK=32.
// If C2 != null: blocks with bcol>=128 write C2 at (bcol-128), row stride ldc.
__global__ void __launch_bounds__(256, 2)
mma_gemm(const float* __restrict__ A, const float* __restrict__ Bm,
         float* __restrict__ C, float* __restrict__ C2,
         const float* __restrict__ bias,
         int M, int N, int K, int ldc, int act) {
    __shared__ unsigned As[128][36];
    __shared__ unsigned Bs[32][136];

    const int tid  = threadIdx.x;
    const int warp = tid >> 5;
    const int lane = tid & 31;
    const int wm   = (warp >> 1) * 32;
    const int wn   = (warp & 1) * 64;
    const int g    = lane >> 2;
    const int tg   = lane & 3;
    const int brow = blockIdx.y * 128;
    const int bcol = blockIdx.x * 128;

    float* Cb = C;
    int cb = bcol;
    if (C2 && bcol >= 128) { Cb = C2; cb = bcol - 128; }

    float acc[2][8][4];
#pragma unroll
    for (int i = 0; i < 2; i++)
#pragma unroll
        for (int j = 0; j < 8; j++)
#pragma unroll
            for (int q = 0; q < 4; q++) acc[i][j][q] = 0.f;

    const int arow   = tid >> 3;
    const int acol   = (tid & 7) * 4;
    const int brow_l = tid >> 5;
    const int bcol_l = (tid & 31) * 4;

    for (int k0 = 0; k0 < K; k0 += 32) {
#pragma unroll
        for (int i = 0; i < 4; i++) {
            int r = arow + i * 32;
            int grow = brow + r;
            float4 v = (grow < M) ? *(const float4*)(A + (size_t)grow * K + k0 + acol)
                                  : make_float4(0.f, 0.f, 0.f, 0.f);
            As[r][acol + 0] = f2tf32(v.x);
            As[r][acol + 1] = f2tf32(v.y);
            As[r][acol + 2] = f2tf32(v.z);
            As[r][acol + 3] = f2tf32(v.w);
        }
#pragma unroll
        for (int i = 0; i < 4; i++) {
            int r = brow_l + i * 8;
            float4 v = *(const float4*)(Bm + (size_t)(k0 + r) * N + bcol + bcol_l);
            Bs[r][bcol_l + 0] = f2tf32(v.x);
            Bs[r][bcol_l + 1] = f2tf32(v.y);
            Bs[r][bcol_l + 2] = f2tf32(v.z);
            Bs[r][bcol_l + 3] = f2tf32(v.w);
        }
        __syncthreads();

#pragma unroll
        for (int ks = 0; ks < 4; ks++) {
            const int kk = ks * 8;
            unsigned a[2][4], b[8][2];
#pragma unroll
            for (int mt = 0; mt < 2; mt++) {
                int rm = wm + mt * 16 + g;
                a[mt][0] = As[rm][kk + tg];
                a[mt][1] = As[rm + 8][kk + tg];
                a[mt][2] = As[rm][kk + tg + 4];
                a[mt][3] = As[rm + 8][kk + tg + 4];
            }
#pragma unroll
            for (int nt = 0; nt < 8; nt++) {
                int cn = wn + nt * 8 + g;
                b[nt][0] = Bs[kk + tg][cn];
                b[nt][1] = Bs[kk + tg + 4][cn];
            }
#pragma unroll
            for (int mt = 0; mt < 2; mt++)
#pragma unroll
                for (int nt = 0; nt < 8; nt++) {
                    asm volatile(
                        "mma.sync.aligned.m16n8k8.row.col.f32.tf32.tf32.f32 "
                        "{%0,%1,%2,%3}, {%4,%5,%6,%7}, {%8,%9}, {%0,%1,%2,%3};\n"
                        : "+f"(acc[mt][nt][0]), "+f"(acc[mt][nt][1]),
                          "+f"(acc[mt][nt][2]), "+f"(acc[mt][nt][3])
                        : "r"(a[mt][0]), "r"(a[mt][1]), "r"(a[mt][2]), "r"(a[mt][3]),
                          "r"(b[nt][0]), "r"(b[nt][1]));
                }
        }
        __syncthreads();
    }

#pragma unroll
    for (int mt = 0; mt < 2; mt++) {
        int r0 = brow + wm + mt * 16 + g;
        int r1 = r0 + 8;
#pragma unroll
        for (int nt = 0; nt < 8; nt++) {
            int cfull = bcol + wn + nt * 8 + 2 * tg;     // bias index
            int c = cb + wn + nt * 8 + 2 * tg;           // output col
            float b0 = bias[cfull], b1 = bias[cfull + 1];
            float v00 = acc[mt][nt][0] + b0;
            float v01 = acc[mt][nt][1] + b1;
            float v10 = acc[mt][nt][2] + b0;
            float v11 = acc[mt][nt][3] + b1;
            if (act) {
                v00 = v00 / (1.f + expf(-v00));
                v01 = v01 / (1.f + expf(-v01));
                v10 = v10 / (1.f + expf(-v10));
                v11 = v11 / (1.f + expf(-v11));
            }
            if (r0 < M) *(float2*)(Cb + (size_t)r0 * ldc + c) = make_float2(v00, v01);
            if (r1 < M) *(float2*)(Cb + (size_t)r1 * ldc + c) = make_float2(v10, v11);
        }
    }
}

// ---------------- LayerNorm (warp per node); optional residual add ----------------
__global__ void ln_kernel(const float* __restrict__ in, const float* __restrict__ res,
                          const float* __restrict__ g, const float* __restrict__ b,
                          float* __restrict__ out, int n) {
    int warp = (blockIdx.x * blockDim.x + threadIdx.x) >> 5;
    int lane = threadIdx.x & 31;
    if (warp >= n) return;
    float4 v = ((const float4*)(in + (size_t)warp * 128))[lane];
    if (res) {
        float4 r = ((const float4*)(res + (size_t)warp * 128))[lane];
        v.x += r.x; v.y += r.y; v.z += r.z; v.w += r.w;
    }
    float s  = v.x + v.y + v.z + v.w;
    float sq = v.x * v.x + v.y * v.y + v.z * v.z + v.w * v.w;
#pragma unroll
    for (int o = 16; o; o >>= 1) {
        s  += __shfl_xor_sync(0xffffffffu, s, o);
        sq += __shfl_xor_sync(0xffffffffu, sq, o);
    }
    float mu = s * (1.f / 128.f);
    float var = sq * (1.f / 128.f) - mu * mu;
    float rstd = rsqrtf(var + 1e-5f);
    float4 gg = ((const float4*)g)[lane];
    float4 bb = ((const float4*)b)[lane];
    float4 o4;
    o4.x = (v.x - mu) * rstd * gg.x + bb.x;
    o4.y = (v.y - mu) * rstd * gg.y + bb.y;
    o4.z = (v.z - mu) * rstd * gg.z + bb.z;
    o4.w = (v.w - mu) * rstd * gg.w + bb.w;
    ((float4*)(out + (size_t)warp * 128))[lane] = o4;
}

// ---------------- launch ----------------
extern "C" void kernel_launch(void* const* d_in, const int* in_sizes, int n_in,
                              void* d_out, int out_size) {
    const float* x        = (const float*)d_in[0];
    const int*   ei       = (const int*)  d_in[1];
    const float* Wl       = (const float*)d_in[2];
    const float* bl       = (const float*)d_in[3];
    const float* Wr       = (const float*)d_in[4];
    const float* br       = (const float*)d_in[5];
    const float* att      = (const float*)d_in[6];
    const float* bias_gat = (const float*)d_in[7];
    const float* g1       = (const float*)d_in[8];
    const float* bn1      = (const float*)d_in[9];
    const float* W1       = (const float*)d_in[10];
    const float* bW1      = (const float*)d_in[11];
    const float* W2       = (const float*)d_in[12];
    const float* bW2      = (const float*)d_in[13];
    const float* g2       = (const float*)d_in[14];
    const float* bn2      = (const float*)d_in[15];
    float* out = (float*)d_out;

    const int n = in_sizes[0] / FDIM;      // 100000
    const int E = in_sizes[1] / 2;         // 1600000

    float *p_xl, *p_xr, *p_t, *p_u, *p_v, *p_h, *p_wcat, *p_bcat;
    int *p_deg;
    cudaGetSymbolAddress((void**)&p_xl,   g_xl);
    cudaGetSymbolAddress((void**)&p_xr,   g_xr);
    cudaGetSymbolAddress((void**)&p_t,    g_t);
    cudaGetSymbolAddress((void**)&p_u,    g_u);
    cudaGetSymbolAddress((void**)&p_v,    g_v);
    cudaGetSymbolAddress((void**)&p_h,    g_h);
    cudaGetSymbolAddress((void**)&p_wcat, g_wcat);
    cudaGetSymbolAddress((void**)&p_bcat, g_bcat);
    cudaGetSymbolAddress((void**)&p_deg,  g_deg);

    const int scan_blocks = (n + 255) / 256;

    prep_wcat<<<(FDIM * 256 + 255) / 256, 256>>>(Wl, Wr, bl, br);
    cudaMemsetAsync(p_deg, 0, (size_t)n * sizeof(int), 0);

    k_hist<<<(E + 255) / 256, 256>>>(ei, E);
    k_scan1<<<scan_blocks, 256>>>(n);
    k_scan2<<<1, 1024>>>(scan_blocks);
    k_scan3<<<scan_blocks, 256>>>(n);
    k_scatter<<<(E + 255) / 256, 256>>>(ei, E);

    const int MB = (n + 127) / 128;

    // 1) [xl|xr] = x @ [Wl|Wr] + [bl|br]  (tf32, split outputs)
    mma_gemm<<<dim3(2, MB), 256>>>(x, p_wcat, p_xl, p_xr, p_bcat, n, 256, 128, 128, 0);

    // 2) fused GAT gather + LN1
    k_gather_ln<<<(n + 7) / 8, 256>>>(att, bias_gat, g1, bn1, n);

    // 3) u = silu(t @ W1 + bW1)  (tf32)
    mma_gemm<<<dim3(4, MB), 256>>>(p_t, W1, p_u, nullptr, bW1, n, 512, 128, 512, 1);

    // 4) v = u @ W2 + bW2        (tf32)
    mma_gemm<<<dim3(1, MB), 256>>>(p_u, W2, p_v, nullptr, bW2, n, 128, 512, 128, 0);

    // 5) out = LN2(h + v)
    ln_kernel<<<(n + 7) / 8, 256>>>(p_h, p_v, g2, bn2, out, n);
}